// round 9
// baseline (speedup 1.0000x reference)
#include <cuda_runtime.h>
#include <cuda_fp16.h>
#include <cstdint>
#include <cstddef>

// ---------------------------------------------------------------------------
// Problem constants
// ---------------------------------------------------------------------------
static constexpr int OUT_F  = 4096;
static constexpr int IN_F   = 4096;
static constexpr int TOKENS = 8192;
static constexpr size_t NELEM = (size_t)OUT_F * IN_F;       // 16,777,216
static constexpr size_t XELEM = (size_t)TOKENS * IN_F;      // 33,554,432

// Scratch in __device__ globals (no cudaMalloc allowed).
__device__ __align__(256) __half g_W[NELEM];                // dequantized weights (fp16)
__device__ __align__(256) __half g_X[XELEM];                // activations fp32 -> fp16

// ---------------------------------------------------------------------------
// Kernel 1 (merged prep): block range [0, DQ_BLOCKS) dequantizes nibbles,
// [DQ_BLOCKS, DQ_BLOCKS+CVT_BLOCKS) converts activations fp32 -> fp16.
// Merging overlaps the two memory phases and drops one launch.
// ---------------------------------------------------------------------------
static constexpr int DQ_BLOCKS  = (int)(NELEM / 8 / 256);   // 8192
static constexpr int CVT_BLOCKS = (int)(XELEM / 8 / 256);   // 16384

__global__ void prep_kernel(const int* __restrict__ qw,
                            const int* __restrict__ am1,
                            const float* __restrict__ code1,
                            const float* __restrict__ off1,
                            const float* __restrict__ am2,
                            const float* __restrict__ code2,
                            const float* __restrict__ X) {
    if (blockIdx.x < DQ_BLOCKS) {
        int i = blockIdx.x * 256 + threadIdx.x;             // over NELEM/8
        int4 p = reinterpret_cast<const int4*>(qw)[i];      // 4 packed bytes -> 8 elems
        int b1 = i >> 3;
        int b2 = i >> 5;
        float s1 = (float)am1[b1] / code1[b1];
        float o  = off1[b1];
        float s2 = am2[b2] / code2[b2];

        __half h[8];
        int bs[4] = {p.x, p.y, p.z, p.w};
#pragma unroll
        for (int j = 0; j < 4; ++j) {
            float lo = (float)(bs[j] & 15);
            float hi = (float)((bs[j] >> 4) & 15);
            h[2*j+0] = __float2half_rn(((lo - o) * s1) * s2);
            h[2*j+1] = __float2half_rn(((hi - o) * s1) * s2);
        }
        reinterpret_cast<int4*>(g_W)[i] = *reinterpret_cast<int4*>(h);
    } else {
        size_t i = (size_t)(blockIdx.x - DQ_BLOCKS) * 256 + threadIdx.x; // over XELEM/8
        const float4* src = reinterpret_cast<const float4*>(X) + i * 2;
        float4 f0 = src[0];
        float4 f1 = src[1];
        __half h[8];
        h[0] = __float2half_rn(f0.x); h[1] = __float2half_rn(f0.y);
        h[2] = __float2half_rn(f0.z); h[3] = __float2half_rn(f0.w);
        h[4] = __float2half_rn(f1.x); h[5] = __float2half_rn(f1.y);
        h[6] = __float2half_rn(f1.z); h[7] = __float2half_rn(f1.w);
        reinterpret_cast<int4*>(g_X)[i] = *reinterpret_cast<int4*>(h);
    }
}

// ---------------------------------------------------------------------------
// Kernel 2: GEMM  out[m,n] = sum_k x[m,k] * W[n,k]  (fp16 in, fp32 acc, fp32 out)
// ldmatrix + mma.m16n8k16, cp.async 4-stage pipeline, SW128 swizzled SMEM.
// CTA tile 256(M) x 128(N), BK=64. 512 threads = 16 warps (4x4), warp 64x32.
// R8: register double-buffered fragments (prefetch ks+1 during ks HMMAs).
// ---------------------------------------------------------------------------
static constexpr int BM = 256, BN = 128, BK = 64;
static constexpr int KT = IN_F / BK;                        // 64 k-stages
static constexpr int STAGES = 4;
static constexpr int A_BYTES = BM * 128;                    // 32768
static constexpr int B_BYTES = BN * 128;                    // 16384
static constexpr int STG = A_BYTES + B_BYTES;               // 49152
static constexpr int SMEM_TOTAL = STAGES * STG;             // 196608

#define SWZ(o) ((o) ^ (((o) >> 3) & 0x70))

__device__ __forceinline__ uint32_t smem_u32(const void* p) {
    uint32_t a;
    asm("{ .reg .u64 t; cvta.to.shared.u64 t, %1; cvt.u32.u64 %0, t; }" : "=r"(a) : "l"(p));
    return a;
}
__device__ __forceinline__ void cp16(uint32_t dst, const void* src) {
    asm volatile("cp.async.cg.shared.global [%0], [%1], 16;" :: "r"(dst), "l"(src));
}
__device__ __forceinline__ void ldsm4(uint32_t* r, uint32_t addr) {
    asm volatile("ldmatrix.sync.aligned.m8n8.x4.shared.b16 {%0,%1,%2,%3}, [%4];"
                 : "=r"(r[0]), "=r"(r[1]), "=r"(r[2]), "=r"(r[3]) : "r"(addr));
}
__device__ __forceinline__ void mma16816(float* c, const uint32_t* a,
                                         uint32_t b0, uint32_t b1) {
    asm volatile(
        "mma.sync.aligned.m16n8k16.row.col.f32.f16.f16.f32 "
        "{%0,%1,%2,%3}, {%4,%5,%6,%7}, {%8,%9}, {%0,%1,%2,%3};"
        : "+f"(c[0]), "+f"(c[1]), "+f"(c[2]), "+f"(c[3])
        : "r"(a[0]), "r"(a[1]), "r"(a[2]), "r"(a[3]), "r"(b0), "r"(b1));
}

// Load one k-stage. A: 256 rows x 8 x 16B (2048 chunks), B: 128 x 8 (1024).
// 512 threads -> 6 cp.async each. gA/gB pre-offset to (tile_row0, k0).
__device__ __forceinline__ void load_stage(uint32_t sA, uint32_t sB,
                                           const __half* gA, const __half* gB, int tid) {
#pragma unroll
    for (int it = 0; it < 4; ++it) {
        int c = tid + it * 512;
        int row = c >> 3, cc = c & 7;
        cp16(sA + SWZ(row * 128 + cc * 16), gA + (size_t)row * IN_F + cc * 8);
    }
#pragma unroll
    for (int it = 0; it < 2; ++it) {
        int c = tid + it * 512;
        int row = c >> 3, cc = c & 7;
        cp16(sB + SWZ(row * 128 + cc * 16), gB + (size_t)row * IN_F + cc * 8);
    }
}

__global__ void __launch_bounds__(512, 1) gemm_kernel(float* __restrict__ OUT) {
    extern __shared__ __align__(1024) char smem[];
    const uint32_t sb = smem_u32(smem);
    const int tid  = threadIdx.x;
    const int wid  = tid >> 5, lane = tid & 31;
    const int wm   = wid >> 2, wn = wid & 3;                // 4x4 warp grid
    const int m0   = blockIdx.y * BM;
    const int n0   = blockIdx.x * BN;

    const __half* gA = g_X + (size_t)m0 * IN_F;
    const __half* gB = g_W + (size_t)n0 * IN_F;

    // Prologue: stages 0..STAGES-2
#pragma unroll
    for (int t = 0; t < STAGES - 1; ++t) {
        uint32_t s = sb + t * STG;
        load_stage(s, s + A_BYTES, gA + t * BK, gB + t * BK, tid);
        asm volatile("cp.async.commit_group;" ::: "memory");
    }

    float acc[4][4][4];
#pragma unroll
    for (int i = 0; i < 4; ++i)
#pragma unroll
        for (int j = 0; j < 4; ++j)
#pragma unroll
            for (int r = 0; r < 4; ++r) acc[i][j][r] = 0.0f;

    // Per-lane ldmatrix address components (byte offsets inside a stage).
    // A x4: row = m_base + (lane&15), kbyte += (lane>>4)*16
    const int a_row = wm * 64 + (lane & 15);
    const int a_kb  = (lane >> 4) << 4;
    // B x4: nrow = n_base + ((lane>>4)<<3) + (lane&7), kbyte += ((lane>>3)&1)*16
    const int b_row = wn * 32 + ((lane >> 4) << 3) + (lane & 7);
    const int b_kb  = ((lane >> 3) & 1) << 4;

    for (int kt = 0; kt < KT; ++kt) {
        asm volatile("cp.async.wait_group %0;" :: "n"(STAGES - 2));
        __syncthreads();                                    // stage kt ready; prev compute done

        int tl = kt + STAGES - 1;                           // refills slot consumed at kt-1
        if (tl < KT) {
            uint32_t s = sb + (tl & (STAGES - 1)) * STG;
            load_stage(s, s + A_BYTES, gA + tl * BK, gB + tl * BK, tid);
        }
        asm volatile("cp.async.commit_group;" ::: "memory");

        uint32_t sA = sb + (kt & (STAGES - 1)) * STG;
        uint32_t sB = sA + A_BYTES;

        // Register double-buffered fragment pipeline over the 4 k16 slices.
        uint32_t a[2][4][4], b[2][2][4];
#pragma unroll
        for (int i = 0; i < 4; ++i)
            ldsm4(a[0][i], sA + SWZ((a_row + i * 16) * 128 + a_kb));
#pragma unroll
        for (int p = 0; p < 2; ++p)
            ldsm4(b[0][p], sB + SWZ((b_row + p * 16) * 128 + b_kb));

#pragma unroll
        for (int ks = 0; ks < 4; ++ks) {
            const int cur = ks & 1, nxt = cur ^ 1;
            if (ks < 3) {                                   // prefetch ks+1 fragments
#pragma unroll
                for (int i = 0; i < 4; ++i)
                    ldsm4(a[nxt][i], sA + SWZ((a_row + i * 16) * 128 + (ks + 1) * 32 + a_kb));
#pragma unroll
                for (int p = 0; p < 2; ++p)
                    ldsm4(b[nxt][p], sB + SWZ((b_row + p * 16) * 128 + (ks + 1) * 32 + b_kb));
            }
#pragma unroll
            for (int i = 0; i < 4; ++i)
#pragma unroll
                for (int j = 0; j < 4; ++j) {
                    const uint32_t* bp = b[cur][j >> 1];
                    mma16816(acc[i][j], a[cur][i], bp[(j & 1) * 2], bp[(j & 1) * 2 + 1]);
                }
        }
    }

    // Epilogue: fp32 accumulators -> float2 stores (full 32B sectors per quad).
    const int gid = lane >> 2, tig = lane & 3;
#pragma unroll
    for (int i = 0; i < 4; ++i) {
#pragma unroll
        for (int j = 0; j < 4; ++j) {
            int row = m0 + wm * 64 + i * 16 + gid;
            int col = n0 + wn * 32 + j * 8 + tig * 2;
            float2 f0 = make_float2(acc[i][j][0], acc[i][j][1]);
            float2 f1 = make_float2(acc[i][j][2], acc[i][j][3]);
            *reinterpret_cast<float2*>(OUT + (size_t)row * OUT_F + col)       = f0;
            *reinterpret_cast<float2*>(OUT + (size_t)(row + 8) * OUT_F + col) = f1;
        }
    }
}

// ---------------------------------------------------------------------------
// Launch: merged prep, then GEMM (same stream -> ordered). Graph-capturable.
// ---------------------------------------------------------------------------
extern "C" void kernel_launch(void* const* d_in, const int* in_sizes, int n_in,
                              void* d_out, int out_size) {
    const float* x   = (const float*)d_in[0];               // fp16 canonicalized to fp32
    const int*   qw  = (const int*)d_in[1];
    const int*   am1 = (const int*)d_in[2];
    const float* c1  = (const float*)d_in[3];
    const float* o1  = (const float*)d_in[4];
    const float* am2 = (const float*)d_in[5];
    const float* c2  = (const float*)d_in[6];
    float* out = (float*)d_out;

    (void)in_sizes; (void)n_in; (void)out_size;

    prep_kernel<<<DQ_BLOCKS + CVT_BLOCKS, 256>>>(qw, am1, c1, o1, am2, c2, x);

    cudaFuncSetAttribute(gemm_kernel, cudaFuncAttributeMaxDynamicSharedMemorySize, SMEM_TOTAL);
    gemm_kernel<<<dim3(OUT_F / BN, TOKENS / BM), 512, SMEM_TOTAL>>>(out);
}

// round 12
// speedup vs baseline: 1.1051x; 1.1051x over previous
#include <cuda_runtime.h>
#include <cuda_fp16.h>
#include <cstdint>
#include <cstddef>

// ---------------------------------------------------------------------------
// Problem constants
// ---------------------------------------------------------------------------
static constexpr int OUT_F  = 4096;
static constexpr int IN_F   = 4096;
static constexpr int TOKENS = 8192;
static constexpr size_t NELEM = (size_t)OUT_F * IN_F;       // 16,777,216
static constexpr size_t XELEM = (size_t)TOKENS * IN_F;      // 33,554,432

// Scratch in __device__ globals (no cudaMalloc allowed).
__device__ __align__(256) __half g_W[NELEM];                // dequantized weights (fp16)
__device__ __align__(256) __half g_X[XELEM];                // activations fp32 -> fp16

// ---------------------------------------------------------------------------
// Kernel 1 (merged prep): block range [0, DQ_BLOCKS) dequantizes nibbles,
// [DQ_BLOCKS, DQ_BLOCKS+CVT_BLOCKS) converts activations fp32 -> fp16.
// ---------------------------------------------------------------------------
static constexpr int DQ_BLOCKS  = (int)(NELEM / 8 / 256);   // 8192
static constexpr int CVT_BLOCKS = (int)(XELEM / 8 / 256);   // 16384

__global__ void prep_kernel(const int* __restrict__ qw,
                            const int* __restrict__ am1,
                            const float* __restrict__ code1,
                            const float* __restrict__ off1,
                            const float* __restrict__ am2,
                            const float* __restrict__ code2,
                            const float* __restrict__ X) {
    if (blockIdx.x < DQ_BLOCKS) {
        int i = blockIdx.x * 256 + threadIdx.x;             // over NELEM/8
        int4 p = reinterpret_cast<const int4*>(qw)[i];      // 4 packed bytes -> 8 elems
        int b1 = i >> 3;
        int b2 = i >> 5;
        float s1 = (float)am1[b1] / code1[b1];
        float o  = off1[b1];
        float s2 = am2[b2] / code2[b2];

        __half h[8];
        int bs[4] = {p.x, p.y, p.z, p.w};
#pragma unroll
        for (int j = 0; j < 4; ++j) {
            float lo = (float)(bs[j] & 15);
            float hi = (float)((bs[j] >> 4) & 15);
            h[2*j+0] = __float2half_rn(((lo - o) * s1) * s2);
            h[2*j+1] = __float2half_rn(((hi - o) * s1) * s2);
        }
        reinterpret_cast<int4*>(g_W)[i] = *reinterpret_cast<int4*>(h);
    } else {
        size_t i = (size_t)(blockIdx.x - DQ_BLOCKS) * 256 + threadIdx.x; // over XELEM/8
        const float4* src = reinterpret_cast<const float4*>(X) + i * 2;
        float4 f0 = src[0];
        float4 f1 = src[1];
        __half h[8];
        h[0] = __float2half_rn(f0.x); h[1] = __float2half_rn(f0.y);
        h[2] = __float2half_rn(f0.z); h[3] = __float2half_rn(f0.w);
        h[4] = __float2half_rn(f1.x); h[5] = __float2half_rn(f1.y);
        h[6] = __float2half_rn(f1.z); h[7] = __float2half_rn(f1.w);
        reinterpret_cast<int4*>(g_X)[i] = *reinterpret_cast<int4*>(h);
    }
}

// ---------------------------------------------------------------------------
// Kernel 2: GEMM  out[m,n] = sum_k x[m,k] * W[n,k]  (fp16 in, fp32 acc, fp32 out)
// ldmatrix + mma.m16n8k16, cp.async 3-stage pipeline, SW128 swizzled SMEM.
// R9: CTA tile 128x128, 256 threads (8 warps, 2x4, warp 64x32), 96KB SMEM
// -> 2 CTAs per SM so barrier/load stalls of one CTA are hidden by the other.
// ---------------------------------------------------------------------------
static constexpr int BM = 128, BN = 128, BK = 64;
static constexpr int KT = IN_F / BK;                        // 64 k-stages
static constexpr int STAGES = 3;
static constexpr int A_BYTES = BM * 128;                    // 16384
static constexpr int B_BYTES = BN * 128;                    // 16384
static constexpr int STG = A_BYTES + B_BYTES;               // 32768
static constexpr int SMEM_TOTAL = STAGES * STG;             // 98304

#define SWZ(o) ((o) ^ (((o) >> 3) & 0x70))

__device__ __forceinline__ uint32_t smem_u32(const void* p) {
    uint32_t a;
    asm("{ .reg .u64 t; cvta.to.shared.u64 t, %1; cvt.u32.u64 %0, t; }" : "=r"(a) : "l"(p));
    return a;
}
__device__ __forceinline__ void cp16(uint32_t dst, const void* src) {
    asm volatile("cp.async.cg.shared.global [%0], [%1], 16;" :: "r"(dst), "l"(src));
}
__device__ __forceinline__ void ldsm4(uint32_t* r, uint32_t addr) {
    asm volatile("ldmatrix.sync.aligned.m8n8.x4.shared.b16 {%0,%1,%2,%3}, [%4];"
                 : "=r"(r[0]), "=r"(r[1]), "=r"(r[2]), "=r"(r[3]) : "r"(addr));
}
__device__ __forceinline__ void mma16816(float* c, const uint32_t* a,
                                         uint32_t b0, uint32_t b1) {
    asm volatile(
        "mma.sync.aligned.m16n8k16.row.col.f32.f16.f16.f32 "
        "{%0,%1,%2,%3}, {%4,%5,%6,%7}, {%8,%9}, {%0,%1,%2,%3};"
        : "+f"(c[0]), "+f"(c[1]), "+f"(c[2]), "+f"(c[3])
        : "r"(a[0]), "r"(a[1]), "r"(a[2]), "r"(a[3]), "r"(b0), "r"(b1));
}

// Load one k-stage. A: 128 rows x 8 x 16B (1024 chunks), B: same.
// 256 threads -> 8 cp.async each. gA/gB pre-offset to (tile_row0, k0).
__device__ __forceinline__ void load_stage(uint32_t sA, uint32_t sB,
                                           const __half* gA, const __half* gB, int tid) {
#pragma unroll
    for (int it = 0; it < 4; ++it) {
        int c = tid + it * 256;
        int row = c >> 3, cc = c & 7;
        cp16(sA + SWZ(row * 128 + cc * 16), gA + (size_t)row * IN_F + cc * 8);
    }
#pragma unroll
    for (int it = 0; it < 4; ++it) {
        int c = tid + it * 256;
        int row = c >> 3, cc = c & 7;
        cp16(sB + SWZ(row * 128 + cc * 16), gB + (size_t)row * IN_F + cc * 8);
    }
}

__global__ void __launch_bounds__(256, 2) gemm_kernel(float* __restrict__ OUT) {
    extern __shared__ __align__(1024) char smem[];
    const uint32_t sb = smem_u32(smem);
    const int tid  = threadIdx.x;
    const int wid  = tid >> 5, lane = tid & 31;
    const int wm   = wid >> 2, wn = wid & 3;                // 2x4 warp grid, warp 64x32
    const int m0   = blockIdx.y * BM;
    const int n0   = blockIdx.x * BN;

    const __half* gA = g_X + (size_t)m0 * IN_F;
    const __half* gB = g_W + (size_t)n0 * IN_F;

    // Prologue: stages 0..STAGES-2
#pragma unroll
    for (int t = 0; t < STAGES - 1; ++t) {
        uint32_t s = sb + t * STG;
        load_stage(s, s + A_BYTES, gA + t * BK, gB + t * BK, tid);
        asm volatile("cp.async.commit_group;" ::: "memory");
    }

    float acc[4][4][4];
#pragma unroll
    for (int i = 0; i < 4; ++i)
#pragma unroll
        for (int j = 0; j < 4; ++j)
#pragma unroll
            for (int r = 0; r < 4; ++r) acc[i][j][r] = 0.0f;

    // Per-lane ldmatrix address components (byte offsets inside a stage).
    // A x4: row = m_base + (lane&15), kbyte += (lane>>4)*16
    const int a_row = wm * 64 + (lane & 15);
    const int a_kb  = (lane >> 4) << 4;
    // B x4: nrow = n_base + ((lane>>4)<<3) + (lane&7), kbyte += ((lane>>3)&1)*16
    const int b_row = wn * 32 + ((lane >> 4) << 3) + (lane & 7);
    const int b_kb  = ((lane >> 3) & 1) << 4;

    int stage = 0;
    for (int kt = 0; kt < KT; ++kt) {
        asm volatile("cp.async.wait_group %0;" :: "n"(STAGES - 2));
        __syncthreads();                                    // stage kt ready; prev compute done

        int tl = kt + STAGES - 1;                           // refills slot consumed at kt-1
        if (tl < KT) {
            int fs = stage + (STAGES - 1);
            if (fs >= STAGES) fs -= STAGES;
            uint32_t s = sb + fs * STG;
            load_stage(s, s + A_BYTES, gA + tl * BK, gB + tl * BK, tid);
        }
        asm volatile("cp.async.commit_group;" ::: "memory");

        uint32_t sA = sb + stage * STG;
        uint32_t sB = sA + A_BYTES;
        if (++stage == STAGES) stage = 0;

#pragma unroll
        for (int ks = 0; ks < 4; ++ks) {                    // 4 x k16 per BK=64
            uint32_t a[4][4], b[2][4];
#pragma unroll
            for (int i = 0; i < 4; ++i)
                ldsm4(a[i], sA + SWZ((a_row + i * 16) * 128 + ks * 32 + a_kb));
#pragma unroll
            for (int p = 0; p < 2; ++p)
                ldsm4(b[p], sB + SWZ((b_row + p * 16) * 128 + ks * 32 + b_kb));
#pragma unroll
            for (int i = 0; i < 4; ++i)
#pragma unroll
                for (int j = 0; j < 4; ++j) {
                    const uint32_t* bp = b[j >> 1];
                    mma16816(acc[i][j], a[i], bp[(j & 1) * 2], bp[(j & 1) * 2 + 1]);
                }
        }
    }

    // Epilogue: fp32 accumulators -> float2 stores (full 32B sectors per quad).
    const int gid = lane >> 2, tig = lane & 3;
#pragma unroll
    for (int i = 0; i < 4; ++i) {
#pragma unroll
        for (int j = 0; j < 4; ++j) {
            int row = m0 + wm * 64 + i * 16 + gid;
            int col = n0 + wn * 32 + j * 8 + tig * 2;
            float2 f0 = make_float2(acc[i][j][0], acc[i][j][1]);
            float2 f1 = make_float2(acc[i][j][2], acc[i][j][3]);
            *reinterpret_cast<float2*>(OUT + (size_t)row * OUT_F + col)       = f0;
            *reinterpret_cast<float2*>(OUT + (size_t)(row + 8) * OUT_F + col) = f1;
        }
    }
}

// ---------------------------------------------------------------------------
// Launch: merged prep, then GEMM (same stream -> ordered). Graph-capturable.
// ---------------------------------------------------------------------------
extern "C" void kernel_launch(void* const* d_in, const int* in_sizes, int n_in,
                              void* d_out, int out_size) {
    const float* x   = (const float*)d_in[0];               // fp16 canonicalized to fp32
    const int*   qw  = (const int*)d_in[1];
    const int*   am1 = (const int*)d_in[2];
    const float* c1  = (const float*)d_in[3];
    const float* o1  = (const float*)d_in[4];
    const float* am2 = (const float*)d_in[5];
    const float* c2  = (const float*)d_in[6];
    float* out = (float*)d_out;

    (void)in_sizes; (void)n_in; (void)out_size;

    prep_kernel<<<DQ_BLOCKS + CVT_BLOCKS, 256>>>(qw, am1, c1, o1, am2, c2, x);

    cudaFuncSetAttribute(gemm_kernel, cudaFuncAttributeMaxDynamicSharedMemorySize, SMEM_TOTAL);
    gemm_kernel<<<dim3(OUT_F / BN, TOKENS / BM), 256, SMEM_TOTAL>>>(out);
}